// round 14
// baseline (speedup 1.0000x reference)
#include <cuda_runtime.h>
#include <math.h>

#define BB 2
#define LL 1024
#define DD 1024
#define NN 16
#define RR 64
#define PBM 8     // rows per work item
#define TG 32     // 32 t-groups of 32 steps
#define PGRID 64  // producer blocks (each does 4 work items in t-order)

// scratch (no device allocations allowed)
__device__ float g_delta[BB * LL * DD];
__device__ float g_Bt[BB * LL * NN];
__device__ float g_Ct[BB * LL * NN];
__device__ int   g_cnt[TG];
__device__ int   g_flag[TG];

__device__ __forceinline__ int ld_acquire(const int* p) {
    int v;
    asm volatile("ld.global.acquire.gpu.b32 %0, [%1];" : "=r"(v) : "l"(p) : "memory");
    return v;
}

__global__ void reset_k() {
    int i = threadIdx.x;
    if (i < TG) { g_cnt[i] = 0; g_flag[i] = 0; }
}

// ---------------------------------------------------------------------------
// Producer: 64 grid-strided blocks; work items ordered GROUP-MAJOR so early
// t-groups publish early. Work item w: group g=w/8, sub=w%8 ->
//   m0 = (sub<4) ? g*32 + sub*8 : 1024 + g*32 + (sub-4)*8
// Inner numerics are the R12 producer verbatim (bit-identical chains).
// ---------------------------------------------------------------------------
__global__ void __launch_bounds__(256) producer_k(
    const float* __restrict__ x,   // [2048, 1024]
    const float* __restrict__ W1,  // [1024, 64]
    const float* __restrict__ WB,  // [1024, 16]
    const float* __restrict__ WC,  // [1024, 16]
    const float* __restrict__ W2)  // [64, 1024]
{
    __shared__ float As[PBM][64];
    __shared__ float Ws[64][96];
    __shared__ float Ts[PBM][64];

    int tid = threadIdx.x;
    int tc = tid & 31;
    int tr = tid >> 5;

    for (int w = blockIdx.x; w < 256; w += PGRID) {
        int g   = w >> 3;
        int sub = w & 7;
        int m0  = (sub < 4) ? (g * 32 + sub * 8)
                            : (1024 + g * 32 + (sub - 4) * 8);

        float a0 = 0.f, a1 = 0.f, a2 = 0.f;

        for (int k0 = 0; k0 < 1024; k0 += 64) {
            __syncthreads();
            if (tid < 128) {
                int r = tid >> 4, c = (tid & 15) * 4;
                *(float4*)&As[r][c] = *(const float4*)&x[(size_t)(m0 + r) * 1024 + k0 + c];
            }
#pragma unroll
            for (int j = 0; j < 4; ++j) {
                int idx = (tid + j * 256) * 4;
                int r = idx >> 6, c = idx & 63;
                *(float4*)&Ws[r][c] = *(const float4*)&W1[(size_t)(k0 + r) * 64 + c];
            }
            {
                int r = tid >> 2, c = (tid & 3) * 4;
                *(float4*)&Ws[r][64 + c] = *(const float4*)&WB[(size_t)(k0 + r) * 16 + c];
                *(float4*)&Ws[r][80 + c] = *(const float4*)&WC[(size_t)(k0 + r) * 16 + c];
            }
            __syncthreads();

#pragma unroll
            for (int k = 0; k < 64; ++k) {
                float a = As[tr][k];
                a0 = fmaf(a, Ws[k][tc],      a0);
                a1 = fmaf(a, Ws[k][tc + 32], a1);
                a2 = fmaf(a, Ws[k][tc + 64], a2);
            }
        }

        if (tc < 16) {
            g_Bt[(size_t)(m0 + tr) * 16 + tc] = a2;
        } else {
            g_Ct[(size_t)(m0 + tr) * 16 + (tc - 16)] = a2;
        }
        __syncthreads();
        Ts[tr][tc]      = a0;
        Ts[tr][tc + 32] = a1;
        __syncthreads();

        int c0 = tid * 4;
        float4 acc[PBM];
#pragma unroll
        for (int r = 0; r < PBM; ++r) { acc[r].x = 0.f; acc[r].y = 0.f; acc[r].z = 0.f; acc[r].w = 0.f; }

#pragma unroll 4
        for (int k = 0; k < 64; ++k) {
            float4 wv = *(const float4*)&W2[(size_t)k * 1024 + c0];
#pragma unroll
            for (int r = 0; r < PBM; ++r) {
                float t = Ts[r][k];
                acc[r].x = fmaf(t, wv.x, acc[r].x);
                acc[r].y = fmaf(t, wv.y, acc[r].y);
                acc[r].z = fmaf(t, wv.z, acc[r].z);
                acc[r].w = fmaf(t, wv.w, acc[r].w);
            }
        }

#pragma unroll
        for (int r = 0; r < PBM; ++r) {
            float4 v;
            v.x = fmaxf(acc[r].x, 0.f) + log1pf(expf(-fabsf(acc[r].x)));
            v.y = fmaxf(acc[r].y, 0.f) + log1pf(expf(-fabsf(acc[r].y)));
            v.z = fmaxf(acc[r].z, 0.f) + log1pf(expf(-fabsf(acc[r].z)));
            v.w = fmaxf(acc[r].w, 0.f) + log1pf(expf(-fabsf(acc[r].w)));
            *(float4*)&g_delta[(size_t)(m0 + r) * 1024 + c0] = v;
        }

        // publish this work item toward its t-group (8 items per group)
        __threadfence();
        __syncthreads();
        if (tid == 0) {
            if (atomicAdd(&g_cnt[g], 1) == 7)
                atomicExch(&g_flag[g], 1);
        }
    }
}

// ---------------- sequential resonance scan (R5 FP sequence + group gates) --
__global__ void __launch_bounds__(256, 1) scan_k(
    const float* __restrict__ x, const float* __restrict__ A_log,
    const float* __restrict__ Dskip, float* __restrict__ y)
{
    int tid = threadIdx.x;
    int bid = blockIdx.x;                 // 0..127
    int b = bid >> 6;                     // 0..1
    int d = ((bid & 63) << 4) | (tid >> 4);
    int n = tid & 15;

    float An = expf(A_log[n]);
    float phi = (float)n * 0.39269908169872414f;
    float sphi, cphi;
    sincosf(phi, &sphi, &cphi);
    float hx = __fmul_rn(0.01f, cphi), hy = __fmul_rn(0.01f, sphi);
    float dsk = Dskip[d];

    size_t rowbase = ((size_t)b * LL) * DD + d;
    const float* xp = x + rowbase;
    const float* dp = g_delta + rowbase;
    const float* bp = g_Bt + ((size_t)b * LL) * NN + n;
    const float* cp = g_Ct + ((size_t)b * LL) * NN + n;
    float* yp = y + rowbase;

    // wait for t-group 0 (rows 0..31, both batch halves)
    while (ld_acquire(&g_flag[0]) == 0) { __nanosleep(100); }

    float xv = __ldg(xp);
    float dv = __ldg(dp);
    float bn = __ldg(bp);
    float cn = __ldg(cp);

#pragma unroll 2
    for (int t = 0; t < LL; ++t) {
        int tnext = t + 1;
        if ((tnext & 31) == 0 && tnext < LL) {
            const int* fp = &g_flag[tnext >> 5];
            while (ld_acquire(fp) == 0) { __nanosleep(100); }
        }

        int tn = (t < LL - 1) ? (t + 1) : t;
        float xv2 = __ldg(xp + (size_t)tn * DD);
        float dv2 = __ldg(dp + (size_t)tn * DD);
        float bn2 = __ldg(bp + tn * NN);
        float cn2 = __ldg(cp + tn * NN);

        // ---- fractal_compress(h, e) ----
        float mag = __fsqrt_rn(__fadd_rn(__fadd_rn(__fmul_rn(hx, hx), __fmul_rn(hy, hy)), 1e-8f));
        float ph  = atan2f(hy, __fadd_rn(hx, 1e-10f));
        float e   = __fadd_rn(1.0f, __fmul_rn(dv, An));
        float cm  = fminf(expf(__fmul_rn(e, logf(__fadd_rn(mag, 1e-8f)))), 10.0f);
        float sph, cph;
        sincosf(ph, &sph, &cph);
        float hcx = __fmul_rn(cm, cph);
        float hcy = __fmul_rn(cm, sph);

        // ---- injection on carrier phases ----
        float u   = __fmul_rn(xv, bn);
        float ijx = __fmul_rn(u, cphi);
        float ijy = __fmul_rn(u, sphi);

        // ---- resonance gate: gamma = 0.5 * cos((pa-pb)/2)^2 ----
        float pa = atan2f(ijy, __fadd_rn(ijx, 1e-10f));
        float pb = atan2f(hcy, __fadd_rn(hcx, 1e-10f));
        float cd = cosf(__fmul_rn(__fsub_rn(pa, pb), 0.5f));
        float gam = __fmul_rn(0.5f, __fmul_rn(cd, cd));

        // ---- inject + mag_squash ----
        float sx = __fadd_rn(hcx, __fmul_rn(gam, ijx));
        float sy = __fadd_rn(hcy, __fmul_rn(gam, ijy));
        float sm = __fsqrt_rn(__fadd_rn(__fadd_rn(__fmul_rn(sx, sx), __fmul_rn(sy, sy)), 1e-8f));
        float ps = atan2f(sy, __fadd_rn(sx, 1e-10f));
        float th = tanhf(sm);
        float sps, cps;
        sincosf(ps, &sps, &cps);
        hx = __fmul_rn(th, cps);
        hy = __fmul_rn(th, sps);

        // ---- readout ----
        float v = __fmul_rn(hx, cn);
        v += __shfl_xor_sync(0xffffffffu, v, 8);
        v += __shfl_xor_sync(0xffffffffu, v, 4);
        v += __shfl_xor_sync(0xffffffffu, v, 2);
        v += __shfl_xor_sync(0xffffffffu, v, 1);
        if (n == 0) yp[(size_t)t * DD] = __fadd_rn(__fmul_rn(xv, dsk), v);

        xv = xv2; dv = dv2; bn = bn2; cn = cn2;
    }
}

extern "C" void kernel_launch(void* const* d_in, const int* in_sizes, int n_in,
                              void* d_out, int out_size)
{
    const float *x = 0, *A_log = 0, *W_dt1 = 0, *W_dt2 = 0, *W_B = 0, *W_C = 0, *Dskip = 0;
    for (int i = 0; i < n_in; ++i) {
        const float* p = (const float*)d_in[i];
        int s = in_sizes[i];
        if (s == BB * LL * DD)      { if (!x) x = p; }
        else if (s == NN)           { if (!A_log) A_log = p; }
        else if (s == DD * RR)      { if (!W_dt1) W_dt1 = p; else W_dt2 = p; }
        else if (s == DD * NN)      { if (!W_B) W_B = p; else W_C = p; }
        else if (s == DD)           { if (!Dskip) Dskip = p; }
    }
    float* y = (float*)d_out;

    // flags reset on the main stream (ordered before both branches)
    reset_k<<<1, 32>>>();

    // fork a side stream inside capture via event edges (no allocations)
    cudaStream_t s1;
    cudaStreamCreateWithFlags(&s1, cudaStreamNonBlocking);
    cudaEvent_t ef, ej;
    cudaEventCreateWithFlags(&ef, cudaEventDisableTiming);
    cudaEventCreateWithFlags(&ej, cudaEventDisableTiming);

    cudaEventRecord(ef, 0);
    cudaStreamWaitEvent(s1, ef, 0);

    // staggered producer runs concurrently with the gated scan
    producer_k<<<PGRID, 256, 0, s1>>>(x, W_dt1, W_B, W_C, W_dt2);
    cudaEventRecord(ej, s1);

    scan_k<<<128, 256>>>(x, A_log, Dskip, y);

    // join: main stream completes only after the producer branch
    cudaStreamWaitEvent(0, ej, 0);
}

// round 15
// speedup vs baseline: 1.1631x; 1.1631x over previous
#include <cuda_runtime.h>
#include <math.h>

#define BB 2
#define LL 1024
#define DD 1024
#define NN 16
#define RR 64
#define PBM 8    // rows per phase-1 block

// scratch (no device allocations allowed)
__device__ float g_tmp[BB * LL * RR];
__device__ float g_delta[BB * LL * DD];
__device__ float g_Bt[BB * LL * NN];
__device__ float g_Ct[BB * LL * NN];

// ---------------------------------------------------------------------------
// Phase 1: [tmp | Bt | Ct](8 rows) = x_tile @ [W1|WB|WC]
// block = 128 threads, 2 rows x 3 cols per thread: 5 LDS / 6 FMA per k
// (vs 4 LDS / 3 FMA before) -> lower smem-crossbar pressure per output.
// Exact k-ascending single-accumulator fmaf chains => bit-identical.
// ---------------------------------------------------------------------------
__global__ void __launch_bounds__(128) phase1_k(
    const float* __restrict__ x,   // [2048, 1024]
    const float* __restrict__ W1,  // [1024, 64]
    const float* __restrict__ WB,  // [1024, 16]
    const float* __restrict__ WC)  // [1024, 16]
{
    __shared__ float As[PBM][64];   // 2 KB
    __shared__ float Ws[64][96];    // 24 KB

    int tid = threadIdx.x;          // 0..127
    int m0 = blockIdx.x * PBM;

    int tc = tid & 31;              // cols tc, tc+32, tc+64
    int r0 = (tid >> 5) * 2;        // rows r0, r0+1

    float a00 = 0.f, a01 = 0.f, a02 = 0.f;   // row r0
    float a10 = 0.f, a11 = 0.f, a12 = 0.f;   // row r0+1

    for (int k0 = 0; k0 < 1024; k0 += 64) {
        __syncthreads();
        // stage x tile 8x64 (one float4 per thread)
        {
            int r = tid >> 4, c = (tid & 15) * 4;
            *(float4*)&As[r][c] = *(const float4*)&x[(size_t)(m0 + r) * 1024 + k0 + c];
        }
        // stage W1 chunk 64x64 (8 float4 per thread)
#pragma unroll
        for (int j = 0; j < 8; ++j) {
            int idx = (tid + j * 128) * 4;
            int r = idx >> 6, c = idx & 63;
            *(float4*)&Ws[r][c] = *(const float4*)&W1[(size_t)(k0 + r) * 64 + c];
        }
        // stage WB/WC chunks 64x16 (2 float4 per thread each)
#pragma unroll
        for (int j = 0; j < 2; ++j) {
            int idx = (tid + j * 128) * 4;
            int r = idx >> 4, c = idx & 15;
            *(float4*)&Ws[r][64 + c] = *(const float4*)&WB[(size_t)(k0 + r) * 16 + c];
            *(float4*)&Ws[r][80 + c] = *(const float4*)&WC[(size_t)(k0 + r) * 16 + c];
        }
        __syncthreads();

#pragma unroll
        for (int k = 0; k < 64; ++k) {
            float w0 = Ws[k][tc], w1 = Ws[k][tc + 32], w2 = Ws[k][tc + 64];
            float ar0 = As[r0][k], ar1 = As[r0 + 1][k];
            a00 = fmaf(ar0, w0, a00);
            a01 = fmaf(ar0, w1, a01);
            a02 = fmaf(ar0, w2, a02);
            a10 = fmaf(ar1, w0, a10);
            a11 = fmaf(ar1, w1, a11);
            a12 = fmaf(ar1, w2, a12);
        }
    }

    g_tmp[(size_t)(m0 + r0) * 64 + tc]          = a00;
    g_tmp[(size_t)(m0 + r0) * 64 + tc + 32]     = a01;
    g_tmp[(size_t)(m0 + r0 + 1) * 64 + tc]      = a10;
    g_tmp[(size_t)(m0 + r0 + 1) * 64 + tc + 32] = a11;
    if (tc < 16) {
        g_Bt[(size_t)(m0 + r0) * 16 + tc]     = a02;
        g_Bt[(size_t)(m0 + r0 + 1) * 16 + tc] = a12;
    } else {
        g_Ct[(size_t)(m0 + r0) * 16 + (tc - 16)]     = a02;
        g_Ct[(size_t)(m0 + r0 + 1) * 16 + (tc - 16)] = a12;
    }
}

// ---------------------------------------------------------------------------
// Phase 2: delta = softplus(tmp @ W_dt2). Classic 64x64 tile, 4x4 register
// block, K=64 in one chunk. Each output: k-ascending fmaf chain + identical
// softplus => bit-identical.
// ---------------------------------------------------------------------------
__global__ void __launch_bounds__(256) delta_k(
    const float* __restrict__ T,   // g_tmp [2048, 64]
    const float* __restrict__ W2)  // [64, 1024]
{
    __shared__ float Ts[64][64];    // 16 KB
    __shared__ float W2s[64][64];   // 16 KB

    int tid = threadIdx.x;
    int mb = blockIdx.y * 64;
    int nb = blockIdx.x * 64;

#pragma unroll
    for (int j = 0; j < 4; ++j) {
        int idx = (tid + j * 256) * 4;
        int r = idx >> 6, c = idx & 63;
        *(float4*)&Ts[r][c]  = *(const float4*)&T[(size_t)(mb + r) * 64 + c];
        *(float4*)&W2s[r][c] = *(const float4*)&W2[(size_t)r * 1024 + nb + c];
    }
    __syncthreads();

    int tr0 = (tid >> 4) * 4;
    int tc0 = (tid & 15) * 4;

    float4 acc[4];
#pragma unroll
    for (int i = 0; i < 4; ++i) { acc[i].x = 0.f; acc[i].y = 0.f; acc[i].z = 0.f; acc[i].w = 0.f; }

#pragma unroll 8
    for (int k = 0; k < 64; ++k) {
        float4 b = *(float4*)&W2s[k][tc0];
#pragma unroll
        for (int i = 0; i < 4; ++i) {
            float a = Ts[tr0 + i][k];
            acc[i].x = fmaf(a, b.x, acc[i].x);
            acc[i].y = fmaf(a, b.y, acc[i].y);
            acc[i].z = fmaf(a, b.z, acc[i].z);
            acc[i].w = fmaf(a, b.w, acc[i].w);
        }
    }

#pragma unroll
    for (int i = 0; i < 4; ++i) {
        float4 v;
        v.x = fmaxf(acc[i].x, 0.f) + log1pf(expf(-fabsf(acc[i].x)));
        v.y = fmaxf(acc[i].y, 0.f) + log1pf(expf(-fabsf(acc[i].y)));
        v.z = fmaxf(acc[i].z, 0.f) + log1pf(expf(-fabsf(acc[i].z)));
        v.w = fmaxf(acc[i].w, 0.f) + log1pf(expf(-fabsf(acc[i].w)));
        *(float4*)&g_delta[(size_t)(mb + tr0 + i) * 1024 + nb + tc0] = v;
    }
}

// ---------------- sequential resonance scan (R5/R12 verbatim — floor) -------
__global__ void __launch_bounds__(256, 1) scan_k(
    const float* __restrict__ x, const float* __restrict__ A_log,
    const float* __restrict__ Dskip, float* __restrict__ y)
{
    int tid = threadIdx.x;
    int bid = blockIdx.x;                 // 0..127
    int b = bid >> 6;                     // 0..1
    int d = ((bid & 63) << 4) | (tid >> 4);
    int n = tid & 15;

    float An = expf(A_log[n]);
    float phi = (float)n * 0.39269908169872414f;
    float sphi, cphi;
    sincosf(phi, &sphi, &cphi);
    float hx = __fmul_rn(0.01f, cphi), hy = __fmul_rn(0.01f, sphi);
    float dsk = Dskip[d];

    size_t rowbase = ((size_t)b * LL) * DD + d;
    const float* xp = x + rowbase;
    const float* dp = g_delta + rowbase;
    const float* bp = g_Bt + ((size_t)b * LL) * NN + n;
    const float* cp = g_Ct + ((size_t)b * LL) * NN + n;
    float* yp = y + rowbase;

    float xv = __ldg(xp);
    float dv = __ldg(dp);
    float bn = __ldg(bp);
    float cn = __ldg(cp);

#pragma unroll 2
    for (int t = 0; t < LL; ++t) {
        int tn = (t < LL - 1) ? (t + 1) : t;
        float xv2 = __ldg(xp + (size_t)tn * DD);
        float dv2 = __ldg(dp + (size_t)tn * DD);
        float bn2 = __ldg(bp + tn * NN);
        float cn2 = __ldg(cp + tn * NN);

        // ---- fractal_compress(h, e) ----
        float mag = __fsqrt_rn(__fadd_rn(__fadd_rn(__fmul_rn(hx, hx), __fmul_rn(hy, hy)), 1e-8f));
        float ph  = atan2f(hy, __fadd_rn(hx, 1e-10f));
        float e   = __fadd_rn(1.0f, __fmul_rn(dv, An));
        float cm  = fminf(expf(__fmul_rn(e, logf(__fadd_rn(mag, 1e-8f)))), 10.0f);
        float sph, cph;
        sincosf(ph, &sph, &cph);
        float hcx = __fmul_rn(cm, cph);
        float hcy = __fmul_rn(cm, sph);

        // ---- injection on carrier phases ----
        float u   = __fmul_rn(xv, bn);
        float ijx = __fmul_rn(u, cphi);
        float ijy = __fmul_rn(u, sphi);

        // ---- resonance gate: gamma = 0.5 * cos((pa-pb)/2)^2 ----
        float pa = atan2f(ijy, __fadd_rn(ijx, 1e-10f));
        float pb = atan2f(hcy, __fadd_rn(hcx, 1e-10f));
        float cd = cosf(__fmul_rn(__fsub_rn(pa, pb), 0.5f));
        float gam = __fmul_rn(0.5f, __fmul_rn(cd, cd));

        // ---- inject + mag_squash ----
        float sx = __fadd_rn(hcx, __fmul_rn(gam, ijx));
        float sy = __fadd_rn(hcy, __fmul_rn(gam, ijy));
        float sm = __fsqrt_rn(__fadd_rn(__fadd_rn(__fmul_rn(sx, sx), __fmul_rn(sy, sy)), 1e-8f));
        float ps = atan2f(sy, __fadd_rn(sx, 1e-10f));
        float th = tanhf(sm);
        float sps, cps;
        sincosf(ps, &sps, &cps);
        hx = __fmul_rn(th, cps);
        hy = __fmul_rn(th, sps);

        // ---- readout ----
        float v = __fmul_rn(hx, cn);
        v += __shfl_xor_sync(0xffffffffu, v, 8);
        v += __shfl_xor_sync(0xffffffffu, v, 4);
        v += __shfl_xor_sync(0xffffffffu, v, 2);
        v += __shfl_xor_sync(0xffffffffu, v, 1);
        if (n == 0) yp[(size_t)t * DD] = __fadd_rn(__fmul_rn(xv, dsk), v);

        xv = xv2; dv = dv2; bn = bn2; cn = cn2;
    }
}

extern "C" void kernel_launch(void* const* d_in, const int* in_sizes, int n_in,
                              void* d_out, int out_size)
{
    const float *x = 0, *A_log = 0, *W_dt1 = 0, *W_dt2 = 0, *W_B = 0, *W_C = 0, *Dskip = 0;
    for (int i = 0; i < n_in; ++i) {
        const float* p = (const float*)d_in[i];
        int s = in_sizes[i];
        if (s == BB * LL * DD)      { if (!x) x = p; }
        else if (s == NN)           { if (!A_log) A_log = p; }
        else if (s == DD * RR)      { if (!W_dt1) W_dt1 = p; else W_dt2 = p; }
        else if (s == DD * NN)      { if (!W_B) W_B = p; else W_C = p; }
        else if (s == DD)           { if (!Dskip) Dskip = p; }
    }
    float* y = (float*)d_out;

    float* tmp;
    cudaGetSymbolAddress((void**)&tmp, g_tmp);

    // phase 1: tmp, Bt, Ct (grid 256, 2 rows x 3 cols per thread)
    phase1_k<<<BB * LL / PBM, 128>>>(x, W_dt1, W_B, W_C);
    // phase 2: delta (classic tiled GEMM, grid 512)
    delta_k<<<dim3(DD / 64, BB * LL / 64), 256>>>(tmp, W_dt2);
    // sequential scan — runs with the machine to itself (co-residency kills it)
    scan_k<<<128, 256>>>(x, A_log, Dskip, y);
}

// round 17
// speedup vs baseline: 1.1803x; 1.0147x over previous
#include <cuda_runtime.h>
#include <math.h>

#define BB 2
#define LL 1024
#define DD 1024
#define NN 16
#define RR 64
#define PBM 8    // rows per phase-1 block

// scratch (no device allocations allowed)
__device__ float g_tmp[BB * LL * RR];
__device__ float g_delta[BB * LL * DD];
__device__ float g_Bt[BB * LL * NN];
__device__ float g_Ct[BB * LL * NN];

// ---------------------------------------------------------------------------
// Phase 1: [tmp | Bt | Ct](8 rows) = x_tile @ [W1|WB|WC]
// 128 threads, 2 rows x 3 cols per thread, register double-buffered staging:
// next chunk's LDGs are issued before this chunk's compute so global latency
// hides under the 64-k FMA loop. Exact k-ascending fmaf chains (bit-identical).
// ---------------------------------------------------------------------------
__global__ void __launch_bounds__(128) phase1_k(
    const float* __restrict__ x,   // [2048, 1024]
    const float* __restrict__ W1,  // [1024, 64]
    const float* __restrict__ WB,  // [1024, 16]
    const float* __restrict__ WC)  // [1024, 16]
{
    __shared__ float As[PBM][64];   // 2 KB
    __shared__ float Ws[64][96];    // 24 KB

    int tid = threadIdx.x;          // 0..127
    int m0 = blockIdx.x * PBM;

    int tc = tid & 31;              // cols tc, tc+32, tc+64
    int r0 = (tid >> 5) * 2;        // rows r0, r0+1

    // staging-role indices (constant across chunks)
    int sar = tid >> 4, sac = (tid & 15) * 4;           // As
    int sw_r[8], sw_c[8];
#pragma unroll
    for (int j = 0; j < 8; ++j) {
        int idx = (tid + j * 128) * 4;
        sw_r[j] = idx >> 6; sw_c[j] = idx & 63;          // W1
    }
    int sb_r[2], sb_c[2];
#pragma unroll
    for (int j = 0; j < 2; ++j) {
        int idx = (tid + j * 128) * 4;
        sb_r[j] = idx >> 4; sb_c[j] = idx & 15;          // WB/WC
    }

    float4 rA, rW[8], rB[2], rC[2];

    // prologue: load chunk 0 into registers
    rA = *(const float4*)&x[(size_t)(m0 + sar) * 1024 + 0 + sac];
#pragma unroll
    for (int j = 0; j < 8; ++j)
        rW[j] = *(const float4*)&W1[(size_t)(0 + sw_r[j]) * 64 + sw_c[j]];
#pragma unroll
    for (int j = 0; j < 2; ++j) {
        rB[j] = *(const float4*)&WB[(size_t)(0 + sb_r[j]) * 16 + sb_c[j]];
        rC[j] = *(const float4*)&WC[(size_t)(0 + sb_r[j]) * 16 + sb_c[j]];
    }

    float a00 = 0.f, a01 = 0.f, a02 = 0.f;
    float a10 = 0.f, a11 = 0.f, a12 = 0.f;

#pragma unroll 1
    for (int c = 0; c < 16; ++c) {
        // store staged registers to smem
        *(float4*)&As[sar][sac] = rA;
#pragma unroll
        for (int j = 0; j < 8; ++j)
            *(float4*)&Ws[sw_r[j]][sw_c[j]] = rW[j];
#pragma unroll
        for (int j = 0; j < 2; ++j) {
            *(float4*)&Ws[sb_r[j]][64 + sb_c[j]] = rB[j];
            *(float4*)&Ws[sb_r[j]][80 + sb_c[j]] = rC[j];
        }
        __syncthreads();

        // issue next chunk's loads (latency hides under the compute below)
        if (c < 15) {
            int k0 = (c + 1) * 64;
            rA = *(const float4*)&x[(size_t)(m0 + sar) * 1024 + k0 + sac];
#pragma unroll
            for (int j = 0; j < 8; ++j)
                rW[j] = *(const float4*)&W1[(size_t)(k0 + sw_r[j]) * 64 + sw_c[j]];
#pragma unroll
            for (int j = 0; j < 2; ++j) {
                rB[j] = *(const float4*)&WB[(size_t)(k0 + sb_r[j]) * 16 + sb_c[j]];
                rC[j] = *(const float4*)&WC[(size_t)(k0 + sb_r[j]) * 16 + sb_c[j]];
            }
        }

#pragma unroll
        for (int k = 0; k < 64; ++k) {
            float w0 = Ws[k][tc], w1 = Ws[k][tc + 32], w2 = Ws[k][tc + 64];
            float ar0 = As[r0][k], ar1 = As[r0 + 1][k];
            a00 = fmaf(ar0, w0, a00);
            a01 = fmaf(ar0, w1, a01);
            a02 = fmaf(ar0, w2, a02);
            a10 = fmaf(ar1, w0, a10);
            a11 = fmaf(ar1, w1, a11);
            a12 = fmaf(ar1, w2, a12);
        }
        __syncthreads();
    }

    g_tmp[(size_t)(m0 + r0) * 64 + tc]          = a00;
    g_tmp[(size_t)(m0 + r0) * 64 + tc + 32]     = a01;
    g_tmp[(size_t)(m0 + r0 + 1) * 64 + tc]      = a10;
    g_tmp[(size_t)(m0 + r0 + 1) * 64 + tc + 32] = a11;
    if (tc < 16) {
        g_Bt[(size_t)(m0 + r0) * 16 + tc]     = a02;
        g_Bt[(size_t)(m0 + r0 + 1) * 16 + tc] = a12;
    } else {
        g_Ct[(size_t)(m0 + r0) * 16 + (tc - 16)]     = a02;
        g_Ct[(size_t)(m0 + r0 + 1) * 16 + (tc - 16)] = a12;
    }
}

// ---------------------------------------------------------------------------
// Phase 2: delta = softplus(tmp @ W_dt2) — R12-style (the fast structure):
// grid 256, 2 KB smem, thread -> 4 cols x 8 rows; W2 streamed from L2.
// Exact k-ascending chains + identical softplus => bit-identical.
// ---------------------------------------------------------------------------
__global__ void __launch_bounds__(256) delta_k(
    const float* __restrict__ T,   // g_tmp [2048, 64]
    const float* __restrict__ W2)  // [64, 1024]
{
    __shared__ float Ts[PBM][64];   // 2 KB

    int tid = threadIdx.x;
    int m0 = blockIdx.x * PBM;

    if (tid < 128) {
        int r = tid >> 4, cc = (tid & 15) * 4;
        *(float4*)&Ts[r][cc] = *(const float4*)&T[(size_t)(m0 + r) * 64 + cc];
    }
    __syncthreads();

    int c0 = tid * 4;
    float4 acc[PBM];
#pragma unroll
    for (int r = 0; r < PBM; ++r) { acc[r].x = 0.f; acc[r].y = 0.f; acc[r].z = 0.f; acc[r].w = 0.f; }

#pragma unroll 4
    for (int k = 0; k < 64; ++k) {
        float4 w = *(const float4*)&W2[(size_t)k * 1024 + c0];
#pragma unroll
        for (int r = 0; r < PBM; ++r) {
            float t = Ts[r][k];
            acc[r].x = fmaf(t, w.x, acc[r].x);
            acc[r].y = fmaf(t, w.y, acc[r].y);
            acc[r].z = fmaf(t, w.z, acc[r].z);
            acc[r].w = fmaf(t, w.w, acc[r].w);
        }
    }

#pragma unroll
    for (int r = 0; r < PBM; ++r) {
        float4 v;
        v.x = fmaxf(acc[r].x, 0.f) + log1pf(expf(-fabsf(acc[r].x)));
        v.y = fmaxf(acc[r].y, 0.f) + log1pf(expf(-fabsf(acc[r].y)));
        v.z = fmaxf(acc[r].z, 0.f) + log1pf(expf(-fabsf(acc[r].z)));
        v.w = fmaxf(acc[r].w, 0.f) + log1pf(expf(-fabsf(acc[r].w)));
        *(float4*)&g_delta[(size_t)(m0 + r) * 1024 + c0] = v;
    }
}

// ---------------- sequential resonance scan (R5/R12 verbatim — floor) -------
__global__ void __launch_bounds__(256, 1) scan_k(
    const float* __restrict__ x, const float* __restrict__ A_log,
    const float* __restrict__ Dskip, float* __restrict__ y)
{
    int tid = threadIdx.x;
    int bid = blockIdx.x;                 // 0..127
    int b = bid >> 6;                     // 0..1
    int d = ((bid & 63) << 4) | (tid >> 4);
    int n = tid & 15;

    float An = expf(A_log[n]);
    float phi = (float)n * 0.39269908169872414f;
    float sphi, cphi;
    sincosf(phi, &sphi, &cphi);
    float hx = __fmul_rn(0.01f, cphi), hy = __fmul_rn(0.01f, sphi);
    float dsk = Dskip[d];

    size_t rowbase = ((size_t)b * LL) * DD + d;
    const float* xp = x + rowbase;
    const float* dp = g_delta + rowbase;
    const float* bp = g_Bt + ((size_t)b * LL) * NN + n;
    const float* cp = g_Ct + ((size_t)b * LL) * NN + n;
    float* yp = y + rowbase;

    float xv = __ldg(xp);
    float dv = __ldg(dp);
    float bn = __ldg(bp);
    float cn = __ldg(cp);

#pragma unroll 2
    for (int t = 0; t < LL; ++t) {
        int tn = (t < LL - 1) ? (t + 1) : t;
        float xv2 = __ldg(xp + (size_t)tn * DD);
        float dv2 = __ldg(dp + (size_t)tn * DD);
        float bn2 = __ldg(bp + tn * NN);
        float cn2 = __ldg(cp + tn * NN);

        // ---- fractal_compress(h, e) ----
        float mag = __fsqrt_rn(__fadd_rn(__fadd_rn(__fmul_rn(hx, hx), __fmul_rn(hy, hy)), 1e-8f));
        float ph  = atan2f(hy, __fadd_rn(hx, 1e-10f));
        float e   = __fadd_rn(1.0f, __fmul_rn(dv, An));
        float cm  = fminf(expf(__fmul_rn(e, logf(__fadd_rn(mag, 1e-8f)))), 10.0f);
        float sph, cph;
        sincosf(ph, &sph, &cph);
        float hcx = __fmul_rn(cm, cph);
        float hcy = __fmul_rn(cm, sph);

        // ---- injection on carrier phases ----
        float u   = __fmul_rn(xv, bn);
        float ijx = __fmul_rn(u, cphi);
        float ijy = __fmul_rn(u, sphi);

        // ---- resonance gate: gamma = 0.5 * cos((pa-pb)/2)^2 ----
        float pa = atan2f(ijy, __fadd_rn(ijx, 1e-10f));
        float pb = atan2f(hcy, __fadd_rn(hcx, 1e-10f));
        float cd = cosf(__fmul_rn(__fsub_rn(pa, pb), 0.5f));
        float gam = __fmul_rn(0.5f, __fmul_rn(cd, cd));

        // ---- inject + mag_squash ----
        float sx = __fadd_rn(hcx, __fmul_rn(gam, ijx));
        float sy = __fadd_rn(hcy, __fmul_rn(gam, ijy));
        float sm = __fsqrt_rn(__fadd_rn(__fadd_rn(__fmul_rn(sx, sx), __fmul_rn(sy, sy)), 1e-8f));
        float ps = atan2f(sy, __fadd_rn(sx, 1e-10f));
        float th = tanhf(sm);
        float sps, cps;
        sincosf(ps, &sps, &cps);
        hx = __fmul_rn(th, cps);
        hy = __fmul_rn(th, sps);

        // ---- readout ----
        float v = __fmul_rn(hx, cn);
        v += __shfl_xor_sync(0xffffffffu, v, 8);
        v += __shfl_xor_sync(0xffffffffu, v, 4);
        v += __shfl_xor_sync(0xffffffffu, v, 2);
        v += __shfl_xor_sync(0xffffffffu, v, 1);
        if (n == 0) yp[(size_t)t * DD] = __fadd_rn(__fmul_rn(xv, dsk), v);

        xv = xv2; dv = dv2; bn = bn2; cn = cn2;
    }
}

extern "C" void kernel_launch(void* const* d_in, const int* in_sizes, int n_in,
                              void* d_out, int out_size)
{
    const float *x = 0, *A_log = 0, *W_dt1 = 0, *W_dt2 = 0, *W_B = 0, *W_C = 0, *Dskip = 0;
    for (int i = 0; i < n_in; ++i) {
        const float* p = (const float*)d_in[i];
        int s = in_sizes[i];
        if (s == BB * LL * DD)      { if (!x) x = p; }
        else if (s == NN)           { if (!A_log) A_log = p; }
        else if (s == DD * RR)      { if (!W_dt1) W_dt1 = p; else W_dt2 = p; }
        else if (s == DD * NN)      { if (!W_B) W_B = p; else W_C = p; }
        else if (s == DD)           { if (!Dskip) Dskip = p; }
    }
    float* y = (float*)d_out;

    float* tmp;
    cudaGetSymbolAddress((void**)&tmp, g_tmp);

    // phase 1: tmp, Bt, Ct (double-buffered staging)
    phase1_k<<<BB * LL / PBM, 128>>>(x, W_dt1, W_B, W_C);
    // phase 2: delta (R12-style fast structure)
    delta_k<<<BB * LL / PBM, 256>>>(tmp, W_dt2);
    // sequential scan — machine to itself
    scan_k<<<128, 256>>>(x, A_log, Dskip, y);
}